// round 7
// baseline (speedup 1.0000x reference)
#include <cuda_runtime.h>
#include <cuda_bf16.h>
#include <math.h>
#include <cstdint>

#define NN 100000
#define NR 8
#define NE 400000
#define DD 128
#define NL 3
#define SLOT 64

// ---------------- device scratch (static, no allocations) ----------------
__device__ float         g_bufA[NN * DD];
__device__ float         g_bufB[NN * DD];
__device__ float         g_el[NR * NN];
__device__ float         g_er[NR * NN];
__device__ float         g_vl[NR * DD];
__device__ float         g_vr[NR * DD];
__device__ __nv_bfloat16 g_whi[NR * DD * DD];
__device__ __nv_bfloat16 g_wlo[NR * DD * DD];
__device__ __nv_bfloat16 g_yhi[(size_t)NR * NN * DD];
__device__ __nv_bfloat16 g_ylo[(size_t)NR * NN * DD];
__device__ int           g_cnt[NR * NN];      // static zero-init; restored by
                                              // last-layer agg each replay
__device__ int           g_slots[(size_t)NR * NN * SLOT];

// ====================== padded adjacency fill (1 launch) ===================
__global__ void fill_padded(const int* __restrict__ esrc,
                            const int* __restrict__ edst) {
    int i = blockIdx.x * 256 + threadIdx.x;
    int r = blockIdx.y;
    if (i >= NE) return;
    int d = edst[(size_t)r * NE + i];
    int s = esrc[(size_t)r * NE + i];
    int pos = atomicAdd(&g_cnt[r * NN + d], 1);
    if (pos < SLOT)
        g_slots[((size_t)r * NN + d) * SLOT + pos] = s;
}

// ---------------- W -> bf16 hi/lo split ------------------------------------
__global__ void prep_w(const float* __restrict__ w) {
    int i = blockIdx.x * 256 + threadIdx.x;
    if (i >= NR * DD * DD) return;
    float v = w[i];
    __nv_bfloat16 hi = __float2bfloat16_rn(v);
    float res = v - __bfloat162float(hi);
    g_whi[i] = hi;
    g_wlo[i] = __float2bfloat16_rn(res);
}

// ---------------- vl[r] = al[r] @ Wsrc[r],  vr[r] = ar[r] @ Wdst[r] -------
__global__ void vecs_kernel(const float* __restrict__ Wsrc,
                            const float* __restrict__ Wdst,
                            const float* __restrict__ al,
                            const float* __restrict__ ar) {
    int b = blockIdx.x;          // 0..15
    int r = b >> 1;
    int k = threadIdx.x;         // 0..127
    const float* W = (b & 1) ? (Wdst + r * DD * DD) : (Wsrc + r * DD * DD);
    const float* a = (b & 1) ? (ar + r * DD) : (al + r * DD);
    float s = 0.f;
#pragma unroll 8
    for (int j = 0; j < DD; j++) s += a[j] * W[j * DD + k];
    float* o = (b & 1) ? g_vr : g_vl;
    o[r * DD + k] = s;
}

// ---------------- el[r][n] = x[n]·vl[r], er[r][n] = x[n]·vr[r] ------------
__global__ void scores_kernel(const float* __restrict__ x) {
    __shared__ float xs[32][133];
    __shared__ float vv[16][DD];
    int tid = threadIdx.x;       // 128 threads
    int n0 = blockIdx.x * 32;

    for (int i = tid; i < 16 * DD; i += 128) {
        int v = i >> 7, k = i & 127;
        vv[v][k] = (v < 8) ? g_vl[v * DD + k] : g_vr[(v - 8) * DD + k];
    }
    for (int i = tid; i < 32 * DD; i += 128) {
        int r = i >> 7, k = i & 127;
        xs[r][k] = x[(size_t)(n0 + r) * DD + k];
    }
    __syncthreads();

    int node = tid & 31;
    int v0 = (tid >> 5) * 4;
    float a0 = 0.f, a1 = 0.f, a2 = 0.f, a3 = 0.f;
#pragma unroll 8
    for (int k = 0; k < DD; k++) {
        float xv = xs[node][k];
        a0 += xv * vv[v0 + 0][k];
        a1 += xv * vv[v0 + 1][k];
        a2 += xv * vv[v0 + 2][k];
        a3 += xv * vv[v0 + 3][k];
    }
    int n = n0 + node;
    float acc[4] = {a0, a1, a2, a3};
#pragma unroll
    for (int j = 0; j < 4; j++) {
        int v = v0 + j;
        if (v < 8) g_el[v * NN + n] = acc[j];
        else       g_er[(v - 8) * NN + n] = acc[j];
    }
}

// =================== aggregation: y[r][d] = softmax-weighted mean ==========
// One warp per (dst, relation). Writes y as bf16 hi/lo directly.
// reset!=0 (last layer): restores g_cnt to 0 for the next graph replay.
__global__ void __launch_bounds__(256)
agg_kernel(const float* __restrict__ x, int reset) {
    const unsigned F = 0xffffffffu;
    int lane = threadIdx.x & 31;
    int d = blockIdx.x * 8 + (threadIdx.x >> 5);
    int r = blockIdx.y;
    if (d >= NN) return;

    int deg = g_cnt[r * NN + d];
    if (deg > SLOT) deg = SLOT;
    if (reset && lane == 0) g_cnt[r * NN + d] = 0;

    const int* row = g_slots + ((size_t)r * NN + d) * SLOT;
    const float* elr = g_el + (size_t)r * NN;
    const float4* x4 = (const float4*)x;

    float ax = 0.f, ay = 0.f, az = 0.f, aw = 0.f;
    float den = 0.f;
    if (deg > 0) {
        float er_d = g_er[(size_t)r * NN + d];
        for (int base = 0; base < deg; base += 32) {
            int c = deg - base;
            if (c > 32) c = 32;
            float w = 0.f;
            int s = 0;
            if (lane < c) {
                s = row[base + lane];
                float v = elr[s] + er_d;
                v = v > 0.f ? v : 0.2f * v;
                w = expf(v);
            }
            float ws = w;
#pragma unroll
            for (int off = 16; off; off >>= 1)
                ws += __shfl_xor_sync(F, ws, off);
            den += ws;
            for (int j = 0; j < c; j++) {
                float wj = __shfl_sync(F, w, j);
                int sj = __shfl_sync(F, s, j);
                float4 xv = x4[(size_t)sj * 32 + lane];
                ax += wj * xv.x;
                ay += wj * xv.y;
                az += wj * xv.z;
                aw += wj * xv.w;
            }
        }
        float inv = 1.f / den;
        ax *= inv; ay *= inv; az *= inv; aw *= inv;
    }
    // bf16 hi/lo split
    __nv_bfloat16 h0 = __float2bfloat16_rn(ax);
    __nv_bfloat16 h1 = __float2bfloat16_rn(ay);
    __nv_bfloat16 h2 = __float2bfloat16_rn(az);
    __nv_bfloat16 h3 = __float2bfloat16_rn(aw);
    __nv_bfloat16 l0 = __float2bfloat16_rn(ax - __bfloat162float(h0));
    __nv_bfloat16 l1 = __float2bfloat16_rn(ay - __bfloat162float(h1));
    __nv_bfloat16 l2 = __float2bfloat16_rn(az - __bfloat162float(h2));
    __nv_bfloat16 l3 = __float2bfloat16_rn(aw - __bfloat162float(h3));
    size_t off = ((size_t)r * NN + d) * DD + lane * 4;
    *(__nv_bfloat162*)(g_yhi + off)     = __nv_bfloat162(h0, h1);
    *(__nv_bfloat162*)(g_yhi + off + 2) = __nv_bfloat162(h2, h3);
    *(__nv_bfloat162*)(g_ylo + off)     = __nv_bfloat162(l0, l1);
    *(__nv_bfloat162*)(g_ylo + off + 2) = __nv_bfloat162(l2, l3);
}

// =================== HMMA GEMM over aggregated y ===========================
// out[m] = [relu]( sum_r y[r][m] @ W[r]^T + bias ).  acc kept in registers
// across all 8 relations; single store, no atomics.  (R5-proven version.)
#define PAD 136   // bf16 elems per smem row

#define SA_HI 0
#define SA_LO (128 * PAD * 2)
#define SB_HI (2 * 128 * PAD * 2)
#define SB_LO (3 * 128 * PAD * 2)
#define SM_TOTAL (4 * 128 * PAD * 2)   // 139264

__device__ __forceinline__ void mma_bf16(float* c, const uint32_t* a,
                                         const uint32_t* b) {
    asm volatile(
        "mma.sync.aligned.m16n8k16.row.col.f32.bf16.bf16.f32 "
        "{%0,%1,%2,%3}, {%4,%5,%6,%7}, {%8,%9}, {%0,%1,%2,%3};"
        : "+f"(c[0]), "+f"(c[1]), "+f"(c[2]), "+f"(c[3])
        : "r"(a[0]), "r"(a[1]), "r"(a[2]), "r"(a[3]), "r"(b[0]), "r"(b[1]));
}

__global__ void __launch_bounds__(256, 1)
gemm_agg_kernel(float* __restrict__ out, const float* __restrict__ bias,
                int relu) {
    extern __shared__ char smem[];
    __nv_bfloat16* Ahi = (__nv_bfloat16*)(smem + SA_HI);
    __nv_bfloat16* Alo = (__nv_bfloat16*)(smem + SA_LO);
    __nv_bfloat16* Bhi = (__nv_bfloat16*)(smem + SB_HI);
    __nv_bfloat16* Blo = (__nv_bfloat16*)(smem + SB_LO);

    int tid = threadIdx.x;
    int wid = tid >> 5;
    int lane = tid & 31;
    int m0 = blockIdx.x * 128;

    int wm = (wid >> 1) * 32;
    int wn = (wid & 1) * 64;
    int g4 = lane >> 2;
    int l4 = (lane & 3) * 2;

    float acc[2][8][4];
#pragma unroll
    for (int mt = 0; mt < 2; mt++)
#pragma unroll
        for (int nt = 0; nt < 8; nt++)
#pragma unroll
            for (int j = 0; j < 4; j++) acc[mt][nt][j] = 0.f;

    for (int r = 0; r < NR; r++) {
        __syncthreads();   // prior MMA done reading smem

        const uint4* whi4 = (const uint4*)(g_whi + (size_t)r * DD * DD);
        const uint4* wlo4 = (const uint4*)(g_wlo + (size_t)r * DD * DD);
        const uint4* yhi4 = (const uint4*)g_yhi;
        const uint4* ylo4 = (const uint4*)g_ylo;
#pragma unroll
        for (int it = 0; it < 8; it++) {
            int idx = tid + it * 256;           // 0..2047
            int row = idx >> 4, c8 = idx & 15;
            *(uint4*)(Bhi + row * PAD + c8 * 8) = whi4[idx];
            *(uint4*)(Blo + row * PAD + c8 * 8) = wlo4[idx];
            uint4 vhi = make_uint4(0, 0, 0, 0), vlo = make_uint4(0, 0, 0, 0);
            if (m0 + row < NN) {
                size_t gi = ((size_t)r * NN + m0 + row) * 16 + c8;
                vhi = yhi4[gi];
                vlo = ylo4[gi];
            }
            *(uint4*)(Ahi + row * PAD + c8 * 8) = vhi;
            *(uint4*)(Alo + row * PAD + c8 * 8) = vlo;
        }
        __syncthreads();

        // ---- 3-term HMMA accumulate ----
#pragma unroll
        for (int kk = 0; kk < 8; kk++) {
            int k = kk * 16;
            uint32_t ahi[2][4], alo[2][4];
#pragma unroll
            for (int mt = 0; mt < 2; mt++) {
                int r0 = wm + mt * 16 + g4;
                const __nv_bfloat16* ph = Ahi + r0 * PAD + k + l4;
                const __nv_bfloat16* pl = Alo + r0 * PAD + k + l4;
                ahi[mt][0] = *(const uint32_t*)(ph);
                ahi[mt][1] = *(const uint32_t*)(ph + 8 * PAD);
                ahi[mt][2] = *(const uint32_t*)(ph + 8);
                ahi[mt][3] = *(const uint32_t*)(ph + 8 * PAD + 8);
                alo[mt][0] = *(const uint32_t*)(pl);
                alo[mt][1] = *(const uint32_t*)(pl + 8 * PAD);
                alo[mt][2] = *(const uint32_t*)(pl + 8);
                alo[mt][3] = *(const uint32_t*)(pl + 8 * PAD + 8);
            }
            uint32_t bhi[8][2], blo[8][2];
#pragma unroll
            for (int nt = 0; nt < 8; nt++) {
                int n = wn + nt * 8 + g4;
                const __nv_bfloat16* ph = Bhi + n * PAD + k + l4;
                const __nv_bfloat16* pl = Blo + n * PAD + k + l4;
                bhi[nt][0] = *(const uint32_t*)(ph);
                bhi[nt][1] = *(const uint32_t*)(ph + 8);
                blo[nt][0] = *(const uint32_t*)(pl);
                blo[nt][1] = *(const uint32_t*)(pl + 8);
            }
#pragma unroll
            for (int mt = 0; mt < 2; mt++)
#pragma unroll
                for (int nt = 0; nt < 8; nt++) {
                    mma_bf16(acc[mt][nt], ahi[mt], bhi[nt]);
                    mma_bf16(acc[mt][nt], ahi[mt], blo[nt]);
                    mma_bf16(acc[mt][nt], alo[mt], bhi[nt]);
                }
        }
    }

    // ---- epilogue: bias (+relu), single store ----
#pragma unroll
    for (int mt = 0; mt < 2; mt++) {
        int row0 = m0 + wm + mt * 16 + g4;
        int row1 = row0 + 8;
#pragma unroll
        for (int nt = 0; nt < 8; nt++) {
            int col = wn + nt * 8 + l4;
            float b0 = bias[col], b1 = bias[col + 1];
            float v0 = acc[mt][nt][0] + b0, v1 = acc[mt][nt][1] + b1;
            float v2 = acc[mt][nt][2] + b0, v3 = acc[mt][nt][3] + b1;
            if (relu) {
                v0 = fmaxf(v0, 0.f); v1 = fmaxf(v1, 0.f);
                v2 = fmaxf(v2, 0.f); v3 = fmaxf(v3, 0.f);
            }
            if (row0 < NN)
                *(float2*)(out + (size_t)row0 * DD + col) = make_float2(v0, v1);
            if (row1 < NN)
                *(float2*)(out + (size_t)row1 * DD + col) = make_float2(v2, v3);
        }
    }
}

// ===========================================================================
extern "C" void kernel_launch(void* const* d_in, const int* in_sizes, int n_in,
                              void* d_out, int out_size) {
    const float* h    = (const float*)d_in[0];
    const int*   esrc = (const int*)d_in[1];
    const int*   edst = (const int*)d_in[2];
    const float* fsw  = (const float*)d_in[3];
    const float* fdw  = (const float*)d_in[4];
    const float* al   = (const float*)d_in[5];
    const float* ar   = (const float*)d_in[6];
    const float* hb   = (const float*)d_in[7];
    float* out_final  = (float*)d_out;

    float *bufA, *bufB;
    cudaGetSymbolAddress((void**)&bufA, g_bufA);
    cudaGetSymbolAddress((void**)&bufB, g_bufB);

    cudaFuncSetAttribute(gemm_agg_kernel,
                         cudaFuncAttributeMaxDynamicSharedMemorySize, SM_TOTAL);

    // launch 1: padded adjacency build (cnt starts 0: static init on first
    // run, restored by last layer's agg on every subsequent replay)
    fill_padded<<<dim3((NE + 255) / 256, NR), 256>>>(esrc, edst);

    const int MT = (NN + 127) / 128;   // 782

    const float* x = h;
    for (int l = 0; l < NL; l++) {
        float* out = (l == 0) ? bufB : (l == 1) ? bufA : out_final;

        prep_w<<<(NR * DD * DD + 255) / 256, 256>>>(fsw + (size_t)l * NR * DD * DD);
        vecs_kernel<<<16, 128>>>(fsw + (size_t)l * NR * DD * DD,
                                 fdw + (size_t)l * NR * DD * DD,
                                 al + l * NR * DD, ar + l * NR * DD);
        scores_kernel<<<NN / 32, 128>>>(x);

        agg_kernel<<<dim3((NN + 7) / 8, NR), 256>>>(x, l == NL - 1 ? 1 : 0);
        gemm_agg_kernel<<<MT, 256, SM_TOTAL>>>(out, hb + l * DD,
                                               l < NL - 1 ? 1 : 0);
        x = out;
    }
}

// round 8
// speedup vs baseline: 1.1713x; 1.1713x over previous
#include <cuda_runtime.h>
#include <cuda_bf16.h>
#include <math.h>
#include <cstdint>

#define NN 100000
#define NR 8
#define NE 400000
#define DD 128
#define NL 3
#define NP1 (NN + 1)

// ---------------- device scratch (static, no allocations) ----------------
__device__ float         g_bufA[NN * DD];
__device__ float         g_bufB[NN * DD];
__device__ float         g_el[NR * NN];
__device__ float         g_er[NR * NN];
__device__ float         g_vl[NR * DD];
__device__ float         g_vr[NR * DD];
__device__ __nv_bfloat16 g_whi[NR * DD * DD];
__device__ __nv_bfloat16 g_wlo[NR * DD * DD];
__device__ __nv_bfloat16 g_yhi[(size_t)NR * NN * DD];
__device__ __nv_bfloat16 g_ylo[(size_t)NR * NN * DD];
__device__ int           g_cnt[NR * NN];    // zero at start; reset by scanA
__device__ int           g_fill[NR * NN];   // zero at start; reset by scanA
__device__ int           g_rowptr[NR * NP1];
__device__ int           g_csrc[(size_t)NR * NE];

// ====================== CSR build: 3 launches ==============================
__global__ void hist_kernel(const int* __restrict__ edst) {
    int i = blockIdx.x * 256 + threadIdx.x;
    int r = blockIdx.y;
    if (i >= NE) return;
    int d = edst[(size_t)r * NE + i];
    atomicAdd(&g_cnt[r * NN + d], 1);
}

// One block per relation: full exclusive scan of g_cnt -> g_rowptr.
// Also resets g_cnt and g_fill to 0 (so the next graph replay starts clean).
#define SCAN_T 1024
#define PER ((NN + SCAN_T - 1) / SCAN_T)   // 98
__global__ void __launch_bounds__(SCAN_T)
scanA_kernel() {
    __shared__ int sh[SCAN_T];
    int r = blockIdx.x;
    int tid = threadIdx.x;
    int i0 = tid * PER;

    // pass 1: chunk sums
    int sum = 0;
    for (int j = 0; j < PER; j++) {
        int i = i0 + j;
        if (i < NN) sum += g_cnt[r * NN + i];
    }
    sh[tid] = sum;
    __syncthreads();
    // Hillis-Steele inclusive scan over 1024 chunk sums
    for (int off = 1; off < SCAN_T; off <<= 1) {
        int t = (tid >= off) ? sh[tid - off] : 0;
        __syncthreads();
        sh[tid] += t;
        __syncthreads();
    }
    int run = sh[tid] - sum;   // exclusive prefix of this chunk
    // pass 2: write rowptr, reset cnt/fill
    for (int j = 0; j < PER; j++) {
        int i = i0 + j;
        if (i < NN) {
            int c = g_cnt[r * NN + i];
            g_rowptr[r * NP1 + i] = run;
            run += c;
            g_cnt[r * NN + i] = 0;
            g_fill[r * NN + i] = 0;
        }
    }
    if (tid == SCAN_T - 1) g_rowptr[r * NP1 + NN] = NE;
}

__global__ void fill_kernel(const int* __restrict__ esrc,
                            const int* __restrict__ edst) {
    int i = blockIdx.x * 256 + threadIdx.x;
    int r = blockIdx.y;
    if (i >= NE) return;
    int d = edst[(size_t)r * NE + i];
    int s = esrc[(size_t)r * NE + i];
    int pos = g_rowptr[r * NP1 + d] + atomicAdd(&g_fill[r * NN + d], 1);
    g_csrc[(size_t)r * NE + pos] = s;
}

// ---------------- fused: W hi/lo split + vl/vr vectors ---------------------
// blocks 0..511: prep_w  (512*256 = 131072 = NR*DD*DD)
// blocks 512..527: vecs  (16 blocks, 128 active threads)
__global__ void prep_wv_kernel(const float* __restrict__ Wsrc,
                               const float* __restrict__ Wdst,
                               const float* __restrict__ al,
                               const float* __restrict__ ar) {
    int b = blockIdx.x;
    if (b < 512) {
        int i = b * 256 + threadIdx.x;
        float v = Wsrc[i];
        __nv_bfloat16 hi = __float2bfloat16_rn(v);
        float res = v - __bfloat162float(hi);
        g_whi[i] = hi;
        g_wlo[i] = __float2bfloat16_rn(res);
    } else if (threadIdx.x < 128) {
        int bb = b - 512;            // 0..15
        int r = bb >> 1;
        int k = threadIdx.x;
        const float* W = (bb & 1) ? (Wdst + r * DD * DD) : (Wsrc + r * DD * DD);
        const float* a = (bb & 1) ? (ar + r * DD) : (al + r * DD);
        float s = 0.f;
#pragma unroll 8
        for (int j = 0; j < DD; j++) s += a[j] * W[j * DD + k];
        float* o = (bb & 1) ? g_vr : g_vl;
        o[r * DD + k] = s;
    }
}

// ---------------- el[r][n] = x[n]·vl[r], er[r][n] = x[n]·vr[r] ------------
__global__ void scores_kernel(const float* __restrict__ x) {
    __shared__ float xs[32][133];
    __shared__ float vv[16][DD];
    int tid = threadIdx.x;       // 128 threads
    int n0 = blockIdx.x * 32;

    for (int i = tid; i < 16 * DD; i += 128) {
        int v = i >> 7, k = i & 127;
        vv[v][k] = (v < 8) ? g_vl[v * DD + k] : g_vr[(v - 8) * DD + k];
    }
    for (int i = tid; i < 32 * DD; i += 128) {
        int r = i >> 7, k = i & 127;
        xs[r][k] = x[(size_t)(n0 + r) * DD + k];
    }
    __syncthreads();

    int node = tid & 31;
    int v0 = (tid >> 5) * 4;
    float a0 = 0.f, a1 = 0.f, a2 = 0.f, a3 = 0.f;
#pragma unroll 8
    for (int k = 0; k < DD; k++) {
        float xv = xs[node][k];
        a0 += xv * vv[v0 + 0][k];
        a1 += xv * vv[v0 + 1][k];
        a2 += xv * vv[v0 + 2][k];
        a3 += xv * vv[v0 + 3][k];
    }
    int n = n0 + node;
    float acc[4] = {a0, a1, a2, a3};
#pragma unroll
    for (int j = 0; j < 4; j++) {
        int v = v0 + j;
        if (v < 8) g_el[v * NN + n] = acc[j];
        else       g_er[(v - 8) * NN + n] = acc[j];
    }
}

// =================== aggregation: y[r][d] = softmax-weighted mean ==========
// One warp per (dst, relation). R5-proven version.
__global__ void __launch_bounds__(256)
agg_kernel(const float* __restrict__ x) {
    const unsigned F = 0xffffffffu;
    int lane = threadIdx.x & 31;
    int d = blockIdx.x * 8 + (threadIdx.x >> 5);
    int r = blockIdx.y;
    if (d >= NN) return;

    const int* rp = g_rowptr + r * NP1;
    const int* cs = g_csrc + (size_t)r * NE;
    const float* elr = g_el + (size_t)r * NN;
    const float4* x4 = (const float4*)x;

    int st = rp[d], en = rp[d + 1];
    float ax = 0.f, ay = 0.f, az = 0.f, aw = 0.f;
    float den = 0.f;
    if (st < en) {
        float er_d = g_er[(size_t)r * NN + d];
        for (int base = st; base < en; base += 32) {
            int c = en - base;
            if (c > 32) c = 32;
            float w = 0.f;
            int s = 0;
            if (lane < c) {
                s = cs[base + lane];
                float v = elr[s] + er_d;
                v = v > 0.f ? v : 0.2f * v;
                w = expf(v);
            }
            float ws = w;
#pragma unroll
            for (int off = 16; off; off >>= 1)
                ws += __shfl_xor_sync(F, ws, off);
            den += ws;
            for (int j = 0; j < c; j++) {
                float wj = __shfl_sync(F, w, j);
                int sj = __shfl_sync(F, s, j);
                float4 xv = x4[(size_t)sj * 32 + lane];
                ax += wj * xv.x;
                ay += wj * xv.y;
                az += wj * xv.z;
                aw += wj * xv.w;
            }
        }
        float inv = 1.f / den;
        ax *= inv; ay *= inv; az *= inv; aw *= inv;
    }
    // bf16 hi/lo split
    __nv_bfloat16 h0 = __float2bfloat16_rn(ax);
    __nv_bfloat16 h1 = __float2bfloat16_rn(ay);
    __nv_bfloat16 h2 = __float2bfloat16_rn(az);
    __nv_bfloat16 h3 = __float2bfloat16_rn(aw);
    __nv_bfloat16 l0 = __float2bfloat16_rn(ax - __bfloat162float(h0));
    __nv_bfloat16 l1 = __float2bfloat16_rn(ay - __bfloat162float(h1));
    __nv_bfloat16 l2 = __float2bfloat16_rn(az - __bfloat162float(h2));
    __nv_bfloat16 l3 = __float2bfloat16_rn(aw - __bfloat162float(h3));
    size_t off = ((size_t)r * NN + d) * DD + lane * 4;
    *(__nv_bfloat162*)(g_yhi + off)     = __nv_bfloat162(h0, h1);
    *(__nv_bfloat162*)(g_yhi + off + 2) = __nv_bfloat162(h2, h3);
    *(__nv_bfloat162*)(g_ylo + off)     = __nv_bfloat162(l0, l1);
    *(__nv_bfloat162*)(g_ylo + off + 2) = __nv_bfloat162(l2, l3);
}

// =================== HMMA GEMM over aggregated y ===========================
// out[m] = [relu]( sum_r y[r][m] @ W[r]^T + bias ).  R5-proven version.
#define PAD 136   // bf16 elems per smem row

#define SA_HI 0
#define SA_LO (128 * PAD * 2)
#define SB_HI (2 * 128 * PAD * 2)
#define SB_LO (3 * 128 * PAD * 2)
#define SM_TOTAL (4 * 128 * PAD * 2)   // 139264

__device__ __forceinline__ void mma_bf16(float* c, const uint32_t* a,
                                         const uint32_t* b) {
    asm volatile(
        "mma.sync.aligned.m16n8k16.row.col.f32.bf16.bf16.f32 "
        "{%0,%1,%2,%3}, {%4,%5,%6,%7}, {%8,%9}, {%0,%1,%2,%3};"
        : "+f"(c[0]), "+f"(c[1]), "+f"(c[2]), "+f"(c[3])
        : "r"(a[0]), "r"(a[1]), "r"(a[2]), "r"(a[3]), "r"(b[0]), "r"(b[1]));
}

__global__ void __launch_bounds__(256, 1)
gemm_agg_kernel(float* __restrict__ out, const float* __restrict__ bias,
                int relu) {
    extern __shared__ char smem[];
    __nv_bfloat16* Ahi = (__nv_bfloat16*)(smem + SA_HI);
    __nv_bfloat16* Alo = (__nv_bfloat16*)(smem + SA_LO);
    __nv_bfloat16* Bhi = (__nv_bfloat16*)(smem + SB_HI);
    __nv_bfloat16* Blo = (__nv_bfloat16*)(smem + SB_LO);

    int tid = threadIdx.x;
    int wid = tid >> 5;
    int lane = tid & 31;
    int m0 = blockIdx.x * 128;

    int wm = (wid >> 1) * 32;
    int wn = (wid & 1) * 64;
    int g4 = lane >> 2;
    int l4 = (lane & 3) * 2;

    float acc[2][8][4];
#pragma unroll
    for (int mt = 0; mt < 2; mt++)
#pragma unroll
        for (int nt = 0; nt < 8; nt++)
#pragma unroll
            for (int j = 0; j < 4; j++) acc[mt][nt][j] = 0.f;

    for (int r = 0; r < NR; r++) {
        __syncthreads();   // prior MMA done reading smem

        const uint4* whi4 = (const uint4*)(g_whi + (size_t)r * DD * DD);
        const uint4* wlo4 = (const uint4*)(g_wlo + (size_t)r * DD * DD);
        const uint4* yhi4 = (const uint4*)g_yhi;
        const uint4* ylo4 = (const uint4*)g_ylo;
#pragma unroll
        for (int it = 0; it < 8; it++) {
            int idx = tid + it * 256;           // 0..2047
            int row = idx >> 4, c8 = idx & 15;
            *(uint4*)(Bhi + row * PAD + c8 * 8) = whi4[idx];
            *(uint4*)(Blo + row * PAD + c8 * 8) = wlo4[idx];
            uint4 vhi = make_uint4(0, 0, 0, 0), vlo = make_uint4(0, 0, 0, 0);
            if (m0 + row < NN) {
                size_t gi = ((size_t)r * NN + m0 + row) * 16 + c8;
                vhi = yhi4[gi];
                vlo = ylo4[gi];
            }
            *(uint4*)(Ahi + row * PAD + c8 * 8) = vhi;
            *(uint4*)(Alo + row * PAD + c8 * 8) = vlo;
        }
        __syncthreads();

        // ---- 3-term HMMA accumulate ----
#pragma unroll
        for (int kk = 0; kk < 8; kk++) {
            int k = kk * 16;
            uint32_t ahi[2][4], alo[2][4];
#pragma unroll
            for (int mt = 0; mt < 2; mt++) {
                int r0 = wm + mt * 16 + g4;
                const __nv_bfloat16* ph = Ahi + r0 * PAD + k + l4;
                const __nv_bfloat16* pl = Alo + r0 * PAD + k + l4;
                ahi[mt][0] = *(const uint32_t*)(ph);
                ahi[mt][1] = *(const uint32_t*)(ph + 8 * PAD);
                ahi[mt][2] = *(const uint32_t*)(ph + 8);
                ahi[mt][3] = *(const uint32_t*)(ph + 8 * PAD + 8);
                alo[mt][0] = *(const uint32_t*)(pl);
                alo[mt][1] = *(const uint32_t*)(pl + 8 * PAD);
                alo[mt][2] = *(const uint32_t*)(pl + 8);
                alo[mt][3] = *(const uint32_t*)(pl + 8 * PAD + 8);
            }
            uint32_t bhi[8][2], blo[8][2];
#pragma unroll
            for (int nt = 0; nt < 8; nt++) {
                int n = wn + nt * 8 + g4;
                const __nv_bfloat16* ph = Bhi + n * PAD + k + l4;
                const __nv_bfloat16* pl = Blo + n * PAD + k + l4;
                bhi[nt][0] = *(const uint32_t*)(ph);
                bhi[nt][1] = *(const uint32_t*)(ph + 8);
                blo[nt][0] = *(const uint32_t*)(pl);
                blo[nt][1] = *(const uint32_t*)(pl + 8);
            }
#pragma unroll
            for (int mt = 0; mt < 2; mt++)
#pragma unroll
                for (int nt = 0; nt < 8; nt++) {
                    mma_bf16(acc[mt][nt], ahi[mt], bhi[nt]);
                    mma_bf16(acc[mt][nt], ahi[mt], blo[nt]);
                    mma_bf16(acc[mt][nt], alo[mt], bhi[nt]);
                }
        }
    }

    // ---- epilogue: bias (+relu), single store ----
#pragma unroll
    for (int mt = 0; mt < 2; mt++) {
        int row0 = m0 + wm + mt * 16 + g4;
        int row1 = row0 + 8;
#pragma unroll
        for (int nt = 0; nt < 8; nt++) {
            int col = wn + nt * 8 + l4;
            float b0 = bias[col], b1 = bias[col + 1];
            float v0 = acc[mt][nt][0] + b0, v1 = acc[mt][nt][1] + b1;
            float v2 = acc[mt][nt][2] + b0, v3 = acc[mt][nt][3] + b1;
            if (relu) {
                v0 = fmaxf(v0, 0.f); v1 = fmaxf(v1, 0.f);
                v2 = fmaxf(v2, 0.f); v3 = fmaxf(v3, 0.f);
            }
            if (row0 < NN)
                *(float2*)(out + (size_t)row0 * DD + col) = make_float2(v0, v1);
            if (row1 < NN)
                *(float2*)(out + (size_t)row1 * DD + col) = make_float2(v2, v3);
        }
    }
}

// ===========================================================================
extern "C" void kernel_launch(void* const* d_in, const int* in_sizes, int n_in,
                              void* d_out, int out_size) {
    const float* h    = (const float*)d_in[0];
    const int*   esrc = (const int*)d_in[1];
    const int*   edst = (const int*)d_in[2];
    const float* fsw  = (const float*)d_in[3];
    const float* fdw  = (const float*)d_in[4];
    const float* al   = (const float*)d_in[5];
    const float* ar   = (const float*)d_in[6];
    const float* hb   = (const float*)d_in[7];
    float* out_final  = (float*)d_out;

    float *bufA, *bufB;
    cudaGetSymbolAddress((void**)&bufA, g_bufA);
    cudaGetSymbolAddress((void**)&bufB, g_bufB);

    cudaFuncSetAttribute(gemm_agg_kernel,
                         cudaFuncAttributeMaxDynamicSharedMemorySize, SM_TOTAL);

    // ---- CSR build: 3 launches (cnt/fill self-resetting via scanA) ----
    hist_kernel<<<dim3((NE + 255) / 256, NR), 256>>>(edst);
    scanA_kernel<<<NR, SCAN_T>>>();
    fill_kernel<<<dim3((NE + 255) / 256, NR), 256>>>(esrc, edst);

    const int MT = (NN + 127) / 128;   // 782

    const float* x = h;
    for (int l = 0; l < NL; l++) {
        float* out = (l == 0) ? bufB : (l == 1) ? bufA : out_final;

        prep_wv_kernel<<<528, 256>>>(fsw + (size_t)l * NR * DD * DD,
                                     fdw + (size_t)l * NR * DD * DD,
                                     al + l * NR * DD, ar + l * NR * DD);
        scores_kernel<<<NN / 32, 128>>>(x);

        agg_kernel<<<dim3((NN + 7) / 8, NR), 256>>>(x);   // launch #6 (layer 0)
        gemm_agg_kernel<<<MT, 256, SM_TOTAL>>>(out, hb + l * DD,
                                               l < NL - 1 ? 1 : 0);
        x = out;
    }
}

// round 9
// speedup vs baseline: 1.2531x; 1.0698x over previous
#include <cuda_runtime.h>
#include <cuda_bf16.h>
#include <math.h>
#include <cstdint>

#define NN 100000
#define NR 8
#define NE 400000
#define DD 128
#define NL 3
#define NP1 (NN + 1)

#define SCAN_B 512
#define NBLK ((NN + SCAN_B - 1) / SCAN_B)   // 196

// ---------------- device scratch (static, no allocations) ----------------
__device__ float         g_bufA[NN * DD];
__device__ float         g_bufB[NN * DD];
__device__ float         g_el[NR * NN];
__device__ float         g_er[NR * NN];
__device__ float         g_vl[NR * DD];
__device__ float         g_vr[NR * DD];
__device__ __nv_bfloat16 g_whi[NR * DD * DD];
__device__ __nv_bfloat16 g_wlo[NR * DD * DD];
__device__ __nv_bfloat16 g_yhi[(size_t)NR * NN * DD];
__device__ __nv_bfloat16 g_ylo[(size_t)NR * NN * DD];
__device__ int           g_cnt[NR * NN];
__device__ int           g_fill[NR * NN];
__device__ int           g_rowptr[NR * NP1];
__device__ int           g_bsum[NR * NBLK];
__device__ int           g_csrc[(size_t)NR * NE];

// ====================== CSR build (R5-proven) ==============================
__global__ void hist_kernel(const int* __restrict__ edst) {
    int i = blockIdx.x * 256 + threadIdx.x;
    int r = blockIdx.y;
    if (i >= NE) return;
    int d = edst[(size_t)r * NE + i];
    atomicAdd(&g_cnt[r * NN + d], 1);
}

__global__ void scan1_kernel() {
    __shared__ int sh[SCAN_B];
    int r = blockIdx.y;
    int tid = threadIdx.x;
    int i = blockIdx.x * SCAN_B + tid;
    int v = (i < NN) ? g_cnt[r * NN + i] : 0;
    sh[tid] = v;
    __syncthreads();
    for (int off = 1; off < SCAN_B; off <<= 1) {
        int t = (tid >= off) ? sh[tid - off] : 0;
        __syncthreads();
        sh[tid] += t;
        __syncthreads();
    }
    int incl = sh[tid];
    if (i < NN) g_rowptr[r * NP1 + i] = incl - v;   // exclusive within block
    if (tid == SCAN_B - 1) g_bsum[r * NBLK + blockIdx.x] = incl;
}

__global__ void scan2_kernel() {
    int r = blockIdx.x;
    if (threadIdx.x != 0) return;
    int run = 0;
    for (int b = 0; b < NBLK; b++) {
        int t = g_bsum[r * NBLK + b];
        g_bsum[r * NBLK + b] = run;
        run += t;
    }
}

__global__ void scan3_kernel() {
    int r = blockIdx.y;
    int i = blockIdx.x * SCAN_B + threadIdx.x;
    if (i < NN) g_rowptr[r * NP1 + i] += g_bsum[r * NBLK + blockIdx.x];
    if (blockIdx.x == 0 && threadIdx.x == 0) g_rowptr[r * NP1 + NN] = NE;
}

__global__ void fill_kernel(const int* __restrict__ esrc,
                            const int* __restrict__ edst) {
    int i = blockIdx.x * 256 + threadIdx.x;
    int r = blockIdx.y;
    if (i >= NE) return;
    int d = edst[(size_t)r * NE + i];
    int s = esrc[(size_t)r * NE + i];
    int pos = g_rowptr[r * NP1 + d] + atomicAdd(&g_fill[r * NN + d], 1);
    g_csrc[(size_t)r * NE + pos] = s;
}

// ---------------- fused: W hi/lo split + vl/vr vectors ---------------------
__global__ void prep_wv_kernel(const float* __restrict__ Wsrc,
                               const float* __restrict__ Wdst,
                               const float* __restrict__ al,
                               const float* __restrict__ ar) {
    int b = blockIdx.x;
    if (b < 512) {
        int i = b * 256 + threadIdx.x;
        float v = Wsrc[i];
        __nv_bfloat16 hi = __float2bfloat16_rn(v);
        float res = v - __bfloat162float(hi);
        g_whi[i] = hi;
        g_wlo[i] = __float2bfloat16_rn(res);
    } else if (threadIdx.x < 128) {
        int bb = b - 512;            // 0..15
        int r = bb >> 1;
        int k = threadIdx.x;
        const float* W = (bb & 1) ? (Wdst + r * DD * DD) : (Wsrc + r * DD * DD);
        const float* a = (bb & 1) ? (ar + r * DD) : (al + r * DD);
        float s = 0.f;
#pragma unroll 8
        for (int j = 0; j < DD; j++) s += a[j] * W[j * DD + k];
        float* o = (bb & 1) ? g_vr : g_vl;
        o[r * DD + k] = s;
    }
}

// ---------------- el[r][n] = x[n]·vl[r], er[r][n] = x[n]·vr[r] ------------
__global__ void scores_kernel(const float* __restrict__ x) {
    __shared__ float xs[32][133];
    __shared__ float vv[16][DD];
    int tid = threadIdx.x;       // 128 threads
    int n0 = blockIdx.x * 32;

    for (int i = tid; i < 16 * DD; i += 128) {
        int v = i >> 7, k = i & 127;
        vv[v][k] = (v < 8) ? g_vl[v * DD + k] : g_vr[(v - 8) * DD + k];
    }
    for (int i = tid; i < 32 * DD; i += 128) {
        int r = i >> 7, k = i & 127;
        xs[r][k] = x[(size_t)(n0 + r) * DD + k];
    }
    __syncthreads();

    int node = tid & 31;
    int v0 = (tid >> 5) * 4;
    float a0 = 0.f, a1 = 0.f, a2 = 0.f, a3 = 0.f;
#pragma unroll 8
    for (int k = 0; k < DD; k++) {
        float xv = xs[node][k];
        a0 += xv * vv[v0 + 0][k];
        a1 += xv * vv[v0 + 1][k];
        a2 += xv * vv[v0 + 2][k];
        a3 += xv * vv[v0 + 3][k];
    }
    int n = n0 + node;
    float acc[4] = {a0, a1, a2, a3};
#pragma unroll
    for (int j = 0; j < 4; j++) {
        int v = v0 + j;
        if (v < 8) g_el[v * NN + n] = acc[j];
        else       g_er[(v - 8) * NN + n] = acc[j];
    }
}

// =================== aggregation: y[r][d] = softmax-weighted mean ==========
// One warp per (dst, relation). 4-deep pipelined gathers (MLP=4).
__global__ void __launch_bounds__(256)
agg_kernel(const float* __restrict__ x) {
    const unsigned F = 0xffffffffu;
    int lane = threadIdx.x & 31;
    int d = blockIdx.x * 8 + (threadIdx.x >> 5);
    int r = blockIdx.y;
    if (d >= NN) return;

    const int* rp = g_rowptr + r * NP1;
    const int* cs = g_csrc + (size_t)r * NE;
    const float* elr = g_el + (size_t)r * NN;
    const float4* x4 = (const float4*)x;

    int st = rp[d], en = rp[d + 1];
    float ax = 0.f, ay = 0.f, az = 0.f, aw = 0.f;
    float den = 0.f;
    if (st < en) {
        float er_d = g_er[(size_t)r * NN + d];
        for (int base = st; base < en; base += 32) {
            int c = en - base;
            if (c > 32) c = 32;
            float w = 0.f;
            int s = 0;
            if (lane < c) {
                s = cs[base + lane];
                float v = elr[s] + er_d;
                v = v > 0.f ? v : 0.2f * v;
                w = expf(v);
            }
            float ws = w;
#pragma unroll
            for (int off = 16; off; off >>= 1)
                ws += __shfl_xor_sync(F, ws, off);
            den += ws;

            // 4-deep pipelined weighted gather (c is warp-uniform)
            for (int j = 0; j < c; j += 4) {
                int rem = c - j;
                float w0, w1 = 0.f, w2 = 0.f, w3 = 0.f;
                float4 v0, v1, v2, v3;
                int s0 = __shfl_sync(F, s, j);
                w0 = __shfl_sync(F, w, j);
                v0 = x4[(size_t)s0 * 32 + lane];
                if (rem > 1) {
                    int s1 = __shfl_sync(F, s, j + 1);
                    w1 = __shfl_sync(F, w, j + 1);
                    v1 = x4[(size_t)s1 * 32 + lane];
                }
                if (rem > 2) {
                    int s2 = __shfl_sync(F, s, j + 2);
                    w2 = __shfl_sync(F, w, j + 2);
                    v2 = x4[(size_t)s2 * 32 + lane];
                }
                if (rem > 3) {
                    int s3 = __shfl_sync(F, s, j + 3);
                    w3 = __shfl_sync(F, w, j + 3);
                    v3 = x4[(size_t)s3 * 32 + lane];
                }
                ax += w0 * v0.x; ay += w0 * v0.y;
                az += w0 * v0.z; aw += w0 * v0.w;
                if (rem > 1) {
                    ax += w1 * v1.x; ay += w1 * v1.y;
                    az += w1 * v1.z; aw += w1 * v1.w;
                }
                if (rem > 2) {
                    ax += w2 * v2.x; ay += w2 * v2.y;
                    az += w2 * v2.z; aw += w2 * v2.w;
                }
                if (rem > 3) {
                    ax += w3 * v3.x; ay += w3 * v3.y;
                    az += w3 * v3.z; aw += w3 * v3.w;
                }
            }
        }
        float inv = 1.f / den;
        ax *= inv; ay *= inv; az *= inv; aw *= inv;
    }
    // bf16 hi/lo split
    __nv_bfloat16 h0 = __float2bfloat16_rn(ax);
    __nv_bfloat16 h1 = __float2bfloat16_rn(ay);
    __nv_bfloat16 h2 = __float2bfloat16_rn(az);
    __nv_bfloat16 h3 = __float2bfloat16_rn(aw);
    __nv_bfloat16 l0 = __float2bfloat16_rn(ax - __bfloat162float(h0));
    __nv_bfloat16 l1 = __float2bfloat16_rn(ay - __bfloat162float(h1));
    __nv_bfloat16 l2 = __float2bfloat16_rn(az - __bfloat162float(h2));
    __nv_bfloat16 l3 = __float2bfloat16_rn(aw - __bfloat162float(h3));
    size_t off = ((size_t)r * NN + d) * DD + lane * 4;
    *(__nv_bfloat162*)(g_yhi + off)     = __nv_bfloat162(h0, h1);
    *(__nv_bfloat162*)(g_yhi + off + 2) = __nv_bfloat162(h2, h3);
    *(__nv_bfloat162*)(g_ylo + off)     = __nv_bfloat162(l0, l1);
    *(__nv_bfloat162*)(g_ylo + off + 2) = __nv_bfloat162(l2, l3);
}

// =================== HMMA GEMM over aggregated y ===========================
// out[m] = [relu]( sum_r y[r][m] @ W[r]^T + bias ).  R5-proven version.
#define PAD 136   // bf16 elems per smem row

#define SA_HI 0
#define SA_LO (128 * PAD * 2)
#define SB_HI (2 * 128 * PAD * 2)
#define SB_LO (3 * 128 * PAD * 2)
#define SM_TOTAL (4 * 128 * PAD * 2)   // 139264

__device__ __forceinline__ void mma_bf16(float* c, const uint32_t* a,
                                         const uint32_t* b) {
    asm volatile(
        "mma.sync.aligned.m16n8k16.row.col.f32.bf16.bf16.f32 "
        "{%0,%1,%2,%3}, {%4,%5,%6,%7}, {%8,%9}, {%0,%1,%2,%3};"
        : "+f"(c[0]), "+f"(c[1]), "+f"(c[2]), "+f"(c[3])
        : "r"(a[0]), "r"(a[1]), "r"(a[2]), "r"(a[3]), "r"(b[0]), "r"(b[1]));
}

__global__ void __launch_bounds__(256, 1)
gemm_agg_kernel(float* __restrict__ out, const float* __restrict__ bias,
                int relu) {
    extern __shared__ char smem[];
    __nv_bfloat16* Ahi = (__nv_bfloat16*)(smem + SA_HI);
    __nv_bfloat16* Alo = (__nv_bfloat16*)(smem + SA_LO);
    __nv_bfloat16* Bhi = (__nv_bfloat16*)(smem + SB_HI);
    __nv_bfloat16* Blo = (__nv_bfloat16*)(smem + SB_LO);

    int tid = threadIdx.x;
    int wid = tid >> 5;
    int lane = tid & 31;
    int m0 = blockIdx.x * 128;

    int wm = (wid >> 1) * 32;
    int wn = (wid & 1) * 64;
    int g4 = lane >> 2;
    int l4 = (lane & 3) * 2;

    float acc[2][8][4];
#pragma unroll
    for (int mt = 0; mt < 2; mt++)
#pragma unroll
        for (int nt = 0; nt < 8; nt++)
#pragma unroll
            for (int j = 0; j < 4; j++) acc[mt][nt][j] = 0.f;

    for (int r = 0; r < NR; r++) {
        __syncthreads();   // prior MMA done reading smem

        const uint4* whi4 = (const uint4*)(g_whi + (size_t)r * DD * DD);
        const uint4* wlo4 = (const uint4*)(g_wlo + (size_t)r * DD * DD);
        const uint4* yhi4 = (const uint4*)g_yhi;
        const uint4* ylo4 = (const uint4*)g_ylo;
#pragma unroll
        for (int it = 0; it < 8; it++) {
            int idx = tid + it * 256;           // 0..2047
            int row = idx >> 4, c8 = idx & 15;
            *(uint4*)(Bhi + row * PAD + c8 * 8) = whi4[idx];
            *(uint4*)(Blo + row * PAD + c8 * 8) = wlo4[idx];
            uint4 vhi = make_uint4(0, 0, 0, 0), vlo = make_uint4(0, 0, 0, 0);
            if (m0 + row < NN) {
                size_t gi = ((size_t)r * NN + m0 + row) * 16 + c8;
                vhi = yhi4[gi];
                vlo = ylo4[gi];
            }
            *(uint4*)(Ahi + row * PAD + c8 * 8) = vhi;
            *(uint4*)(Alo + row * PAD + c8 * 8) = vlo;
        }
        __syncthreads();

        // ---- 3-term HMMA accumulate ----
#pragma unroll
        for (int kk = 0; kk < 8; kk++) {
            int k = kk * 16;
            uint32_t ahi[2][4], alo[2][4];
#pragma unroll
            for (int mt = 0; mt < 2; mt++) {
                int r0 = wm + mt * 16 + g4;
                const __nv_bfloat16* ph = Ahi + r0 * PAD + k + l4;
                const __nv_bfloat16* pl = Alo + r0 * PAD + k + l4;
                ahi[mt][0] = *(const uint32_t*)(ph);
                ahi[mt][1] = *(const uint32_t*)(ph + 8 * PAD);
                ahi[mt][2] = *(const uint32_t*)(ph + 8);
                ahi[mt][3] = *(const uint32_t*)(ph + 8 * PAD + 8);
                alo[mt][0] = *(const uint32_t*)(pl);
                alo[mt][1] = *(const uint32_t*)(pl + 8 * PAD);
                alo[mt][2] = *(const uint32_t*)(pl + 8);
                alo[mt][3] = *(const uint32_t*)(pl + 8 * PAD + 8);
            }
            uint32_t bhi[8][2], blo[8][2];
#pragma unroll
            for (int nt = 0; nt < 8; nt++) {
                int n = wn + nt * 8 + g4;
                const __nv_bfloat16* ph = Bhi + n * PAD + k + l4;
                const __nv_bfloat16* pl = Blo + n * PAD + k + l4;
                bhi[nt][0] = *(const uint32_t*)(ph);
                bhi[nt][1] = *(const uint32_t*)(ph + 8);
                blo[nt][0] = *(const uint32_t*)(pl);
                blo[nt][1] = *(const uint32_t*)(pl + 8);
            }
#pragma unroll
            for (int mt = 0; mt < 2; mt++)
#pragma unroll
                for (int nt = 0; nt < 8; nt++) {
                    mma_bf16(acc[mt][nt], ahi[mt], bhi[nt]);
                    mma_bf16(acc[mt][nt], ahi[mt], blo[nt]);
                    mma_bf16(acc[mt][nt], alo[mt], bhi[nt]);
                }
        }
    }

    // ---- epilogue: bias (+relu), single store ----
#pragma unroll
    for (int mt = 0; mt < 2; mt++) {
        int row0 = m0 + wm + mt * 16 + g4;
        int row1 = row0 + 8;
#pragma unroll
        for (int nt = 0; nt < 8; nt++) {
            int col = wn + nt * 8 + l4;
            float b0 = bias[col], b1 = bias[col + 1];
            float v0 = acc[mt][nt][0] + b0, v1 = acc[mt][nt][1] + b1;
            float v2 = acc[mt][nt][2] + b0, v3 = acc[mt][nt][3] + b1;
            if (relu) {
                v0 = fmaxf(v0, 0.f); v1 = fmaxf(v1, 0.f);
                v2 = fmaxf(v2, 0.f); v3 = fmaxf(v3, 0.f);
            }
            if (row0 < NN)
                *(float2*)(out + (size_t)row0 * DD + col) = make_float2(v0, v1);
            if (row1 < NN)
                *(float2*)(out + (size_t)row1 * DD + col) = make_float2(v2, v3);
        }
    }
}

// ===========================================================================
extern "C" void kernel_launch(void* const* d_in, const int* in_sizes, int n_in,
                              void* d_out, int out_size) {
    const float* h    = (const float*)d_in[0];
    const int*   esrc = (const int*)d_in[1];
    const int*   edst = (const int*)d_in[2];
    const float* fsw  = (const float*)d_in[3];
    const float* fdw  = (const float*)d_in[4];
    const float* al   = (const float*)d_in[5];
    const float* ar   = (const float*)d_in[6];
    const float* hb   = (const float*)d_in[7];
    float* out_final  = (float*)d_out;

    float *bufA, *bufB;
    int *cnt, *fill;
    cudaGetSymbolAddress((void**)&bufA, g_bufA);
    cudaGetSymbolAddress((void**)&bufB, g_bufB);
    cudaGetSymbolAddress((void**)&cnt,  g_cnt);
    cudaGetSymbolAddress((void**)&fill, g_fill);

    cudaFuncSetAttribute(gemm_agg_kernel,
                         cudaFuncAttributeMaxDynamicSharedMemorySize, SM_TOTAL);

    // ---- CSR build (R5-proven parallel scan) ----
    cudaMemsetAsync(cnt, 0, NR * NN * sizeof(int));
    cudaMemsetAsync(fill, 0, NR * NN * sizeof(int));
    hist_kernel<<<dim3((NE + 255) / 256, NR), 256>>>(edst);
    scan1_kernel<<<dim3(NBLK, NR), SCAN_B>>>();
    scan2_kernel<<<NR, 32>>>();
    scan3_kernel<<<dim3(NBLK, NR), SCAN_B>>>();
    fill_kernel<<<dim3((NE + 255) / 256, NR), 256>>>(esrc, edst);

    const int MT = (NN + 127) / 128;   // 782

    const float* x = h;
    for (int l = 0; l < NL; l++) {
        float* out = (l == 0) ? bufB : (l == 1) ? bufA : out_final;

        prep_wv_kernel<<<528, 256>>>(fsw + (size_t)l * NR * DD * DD,
                                     fdw + (size_t)l * NR * DD * DD,
                                     al + l * NR * DD, ar + l * NR * DD);
        scores_kernel<<<NN / 32, 128>>>(x);

        agg_kernel<<<dim3((NN + 7) / 8, NR), 256>>>(x);
        gemm_agg_kernel<<<MT, 256, SM_TOTAL>>>(out, hb + l * DD,
                                               l < NL - 1 ? 1 : 0);
        x = out;
    }
}

// round 10
// speedup vs baseline: 1.2946x; 1.0331x over previous
#include <cuda_runtime.h>
#include <cuda_bf16.h>
#include <math.h>
#include <cstdint>

#define NN 100000
#define NR 8
#define NE 400000
#define DD 128
#define NL 3
#define NP1 (NN + 1)

#define SCAN_B 512
#define NBLK ((NN + SCAN_B - 1) / SCAN_B)   // 196

// ---------------- device scratch (static, no allocations) ----------------
__device__ float         g_bufA[NN * DD];
__device__ float         g_bufB[NN * DD];
__device__ float         g_el[NR * NN];
__device__ float         g_er[NR * NN];
__device__ float         g_vl[NR * DD];
__device__ float         g_vr[NR * DD];
__device__ __nv_bfloat16 g_whi[NR * DD * DD];
__device__ __nv_bfloat16 g_wlo[NR * DD * DD];
__device__ __nv_bfloat16 g_yhi[(size_t)NR * NN * DD];
__device__ __nv_bfloat16 g_ylo[(size_t)NR * NN * DD];
__device__ int           g_cnt[NR * NN];
__device__ int           g_fill[NR * NN];
__device__ int           g_rowptr[NR * NP1];
__device__ int           g_bsum[NR * NBLK];
__device__ int           g_csrc[(size_t)NR * NE];

// ====================== CSR build (R5-proven) ==============================
__global__ void hist_kernel(const int* __restrict__ edst) {
    int i = blockIdx.x * 256 + threadIdx.x;
    int r = blockIdx.y;
    if (i >= NE) return;
    int d = edst[(size_t)r * NE + i];
    atomicAdd(&g_cnt[r * NN + d], 1);
}

__global__ void scan1_kernel() {
    __shared__ int sh[SCAN_B];
    int r = blockIdx.y;
    int tid = threadIdx.x;
    int i = blockIdx.x * SCAN_B + tid;
    int v = (i < NN) ? g_cnt[r * NN + i] : 0;
    sh[tid] = v;
    __syncthreads();
    for (int off = 1; off < SCAN_B; off <<= 1) {
        int t = (tid >= off) ? sh[tid - off] : 0;
        __syncthreads();
        sh[tid] += t;
        __syncthreads();
    }
    int incl = sh[tid];
    if (i < NN) g_rowptr[r * NP1 + i] = incl - v;   // exclusive within block
    if (tid == SCAN_B - 1) g_bsum[r * NBLK + blockIdx.x] = incl;
}

__global__ void scan2_kernel() {
    int r = blockIdx.x;
    if (threadIdx.x != 0) return;
    int run = 0;
    for (int b = 0; b < NBLK; b++) {
        int t = g_bsum[r * NBLK + b];
        g_bsum[r * NBLK + b] = run;
        run += t;
    }
}

__global__ void scan3_kernel() {
    int r = blockIdx.y;
    int i = blockIdx.x * SCAN_B + threadIdx.x;
    if (i < NN) g_rowptr[r * NP1 + i] += g_bsum[r * NBLK + blockIdx.x];
    if (blockIdx.x == 0 && threadIdx.x == 0) g_rowptr[r * NP1 + NN] = NE;
}

__global__ void fill_kernel(const int* __restrict__ esrc,
                            const int* __restrict__ edst) {
    int i = blockIdx.x * 256 + threadIdx.x;
    int r = blockIdx.y;
    if (i >= NE) return;
    int d = edst[(size_t)r * NE + i];
    int s = esrc[(size_t)r * NE + i];
    int pos = g_rowptr[r * NP1 + d] + atomicAdd(&g_fill[r * NN + d], 1);
    g_csrc[(size_t)r * NE + pos] = s;
}

// ---------------- fused: W hi/lo split + vl/vr vectors ---------------------
__global__ void prep_wv_kernel(const float* __restrict__ Wsrc,
                               const float* __restrict__ Wdst,
                               const float* __restrict__ al,
                               const float* __restrict__ ar) {
    int b = blockIdx.x;
    if (b < 512) {
        int i = b * 256 + threadIdx.x;
        float v = Wsrc[i];
        __nv_bfloat16 hi = __float2bfloat16_rn(v);
        float res = v - __bfloat162float(hi);
        g_whi[i] = hi;
        g_wlo[i] = __float2bfloat16_rn(res);
    } else if (threadIdx.x < 128) {
        int bb = b - 512;            // 0..15
        int r = bb >> 1;
        int k = threadIdx.x;
        const float* W = (bb & 1) ? (Wdst + r * DD * DD) : (Wsrc + r * DD * DD);
        const float* a = (bb & 1) ? (ar + r * DD) : (al + r * DD);
        float s = 0.f;
#pragma unroll 8
        for (int j = 0; j < DD; j++) s += a[j] * W[j * DD + k];
        float* o = (bb & 1) ? g_vr : g_vl;
        o[r * DD + k] = s;
    }
}

// ---------------- el[r][n] = x[n]·vl[r], er[r][n] = x[n]·vr[r] ------------
__global__ void scores_kernel(const float* __restrict__ x) {
    __shared__ float xs[32][133];
    __shared__ float vv[16][DD];
    int tid = threadIdx.x;       // 128 threads
    int n0 = blockIdx.x * 32;

    for (int i = tid; i < 16 * DD; i += 128) {
        int v = i >> 7, k = i & 127;
        vv[v][k] = (v < 8) ? g_vl[v * DD + k] : g_vr[(v - 8) * DD + k];
    }
    for (int i = tid; i < 32 * DD; i += 128) {
        int r = i >> 7, k = i & 127;
        xs[r][k] = x[(size_t)(n0 + r) * DD + k];
    }
    __syncthreads();

    int node = tid & 31;
    int v0 = (tid >> 5) * 4;
    float a0 = 0.f, a1 = 0.f, a2 = 0.f, a3 = 0.f;
#pragma unroll 8
    for (int k = 0; k < DD; k++) {
        float xv = xs[node][k];
        a0 += xv * vv[v0 + 0][k];
        a1 += xv * vv[v0 + 1][k];
        a2 += xv * vv[v0 + 2][k];
        a3 += xv * vv[v0 + 3][k];
    }
    int n = n0 + node;
    float acc[4] = {a0, a1, a2, a3};
#pragma unroll
    for (int j = 0; j < 4; j++) {
        int v = v0 + j;
        if (v < 8) g_el[v * NN + n] = acc[j];
        else       g_er[(v - 8) * NN + n] = acc[j];
    }
}

// =================== aggregation: y[r][d] = softmax-weighted mean ==========
// One warp per (dst, relation). R5 simple loop; y written with streaming
// (evict-first) stores so x/el stay L2-resident.
__device__ __forceinline__ uint32_t pack_bf2(__nv_bfloat16 a, __nv_bfloat16 b) {
    return (uint32_t)__bfloat16_as_ushort(a) |
           ((uint32_t)__bfloat16_as_ushort(b) << 16);
}

__global__ void __launch_bounds__(256)
agg_kernel(const float* __restrict__ x) {
    const unsigned F = 0xffffffffu;
    int lane = threadIdx.x & 31;
    int d = blockIdx.x * 8 + (threadIdx.x >> 5);
    int r = blockIdx.y;
    if (d >= NN) return;

    const int* rp = g_rowptr + r * NP1;
    const int* cs = g_csrc + (size_t)r * NE;
    const float* elr = g_el + (size_t)r * NN;
    const float4* x4 = (const float4*)x;

    int st = rp[d], en = rp[d + 1];
    float ax = 0.f, ay = 0.f, az = 0.f, aw = 0.f;
    float den = 0.f;
    if (st < en) {
        float er_d = g_er[(size_t)r * NN + d];
        for (int base = st; base < en; base += 32) {
            int c = en - base;
            if (c > 32) c = 32;
            float w = 0.f;
            int s = 0;
            if (lane < c) {
                s = cs[base + lane];
                float v = elr[s] + er_d;
                v = v > 0.f ? v : 0.2f * v;
                w = expf(v);
            }
            float ws = w;
#pragma unroll
            for (int off = 16; off; off >>= 1)
                ws += __shfl_xor_sync(F, ws, off);
            den += ws;
            for (int j = 0; j < c; j++) {
                float wj = __shfl_sync(F, w, j);
                int sj = __shfl_sync(F, s, j);
                float4 xv = x4[(size_t)sj * 32 + lane];
                ax += wj * xv.x;
                ay += wj * xv.y;
                az += wj * xv.z;
                aw += wj * xv.w;
            }
        }
        float inv = 1.f / den;
        ax *= inv; ay *= inv; az *= inv; aw *= inv;
    }
    // bf16 hi/lo split, streaming stores (evict-first)
    __nv_bfloat16 h0 = __float2bfloat16_rn(ax);
    __nv_bfloat16 h1 = __float2bfloat16_rn(ay);
    __nv_bfloat16 h2 = __float2bfloat16_rn(az);
    __nv_bfloat16 h3 = __float2bfloat16_rn(aw);
    __nv_bfloat16 l0 = __float2bfloat16_rn(ax - __bfloat162float(h0));
    __nv_bfloat16 l1 = __float2bfloat16_rn(ay - __bfloat162float(h1));
    __nv_bfloat16 l2 = __float2bfloat16_rn(az - __bfloat162float(h2));
    __nv_bfloat16 l3 = __float2bfloat16_rn(aw - __bfloat162float(h3));
    size_t off = ((size_t)r * NN + d) * DD + lane * 4;
    __stcs((uint2*)(g_yhi + off), make_uint2(pack_bf2(h0, h1), pack_bf2(h2, h3)));
    __stcs((uint2*)(g_ylo + off), make_uint2(pack_bf2(l0, l1), pack_bf2(l2, l3)));
}

// =================== HMMA GEMM over aggregated y ===========================
// out[m] = [relu]( sum_r y[r][m] @ W[r]^T + bias ).  R5-proven core; y read
// with streaming loads, out written with streaming stores.
#define PAD 136   // bf16 elems per smem row

#define SA_HI 0
#define SA_LO (128 * PAD * 2)
#define SB_HI (2 * 128 * PAD * 2)
#define SB_LO (3 * 128 * PAD * 2)
#define SM_TOTAL (4 * 128 * PAD * 2)   // 139264

__device__ __forceinline__ void mma_bf16(float* c, const uint32_t* a,
                                         const uint32_t* b) {
    asm volatile(
        "mma.sync.aligned.m16n8k16.row.col.f32.bf16.bf16.f32 "
        "{%0,%1,%2,%3}, {%4,%5,%6,%7}, {%8,%9}, {%0,%1,%2,%3};"
        : "+f"(c[0]), "+f"(c[1]), "+f"(c[2]), "+f"(c[3])
        : "r"(a[0]), "r"(a[1]), "r"(a[2]), "r"(a[3]), "r"(b[0]), "r"(b[1]));
}

__global__ void __launch_bounds__(256, 1)
gemm_agg_kernel(float* __restrict__ out, const float* __restrict__ bias,
                int relu) {
    extern __shared__ char smem[];
    __nv_bfloat16* Ahi = (__nv_bfloat16*)(smem + SA_HI);
    __nv_bfloat16* Alo = (__nv_bfloat16*)(smem + SA_LO);
    __nv_bfloat16* Bhi = (__nv_bfloat16*)(smem + SB_HI);
    __nv_bfloat16* Blo = (__nv_bfloat16*)(smem + SB_LO);

    int tid = threadIdx.x;
    int wid = tid >> 5;
    int lane = tid & 31;
    int m0 = blockIdx.x * 128;

    int wm = (wid >> 1) * 32;
    int wn = (wid & 1) * 64;
    int g4 = lane >> 2;
    int l4 = (lane & 3) * 2;

    float acc[2][8][4];
#pragma unroll
    for (int mt = 0; mt < 2; mt++)
#pragma unroll
        for (int nt = 0; nt < 8; nt++)
#pragma unroll
            for (int j = 0; j < 4; j++) acc[mt][nt][j] = 0.f;

    for (int r = 0; r < NR; r++) {
        __syncthreads();   // prior MMA done reading smem

        const uint4* whi4 = (const uint4*)(g_whi + (size_t)r * DD * DD);
        const uint4* wlo4 = (const uint4*)(g_wlo + (size_t)r * DD * DD);
        const uint4* yhi4 = (const uint4*)g_yhi;
        const uint4* ylo4 = (const uint4*)g_ylo;
#pragma unroll
        for (int it = 0; it < 8; it++) {
            int idx = tid + it * 256;           // 0..2047
            int row = idx >> 4, c8 = idx & 15;
            *(uint4*)(Bhi + row * PAD + c8 * 8) = whi4[idx];
            *(uint4*)(Blo + row * PAD + c8 * 8) = wlo4[idx];
            uint4 vhi = make_uint4(0, 0, 0, 0), vlo = make_uint4(0, 0, 0, 0);
            if (m0 + row < NN) {
                size_t gi = ((size_t)r * NN + m0 + row) * 16 + c8;
                vhi = __ldcs(&yhi4[gi]);
                vlo = __ldcs(&ylo4[gi]);
            }
            *(uint4*)(Ahi + row * PAD + c8 * 8) = vhi;
            *(uint4*)(Alo + row * PAD + c8 * 8) = vlo;
        }
        __syncthreads();

        // ---- 3-term HMMA accumulate ----
#pragma unroll
        for (int kk = 0; kk < 8; kk++) {
            int k = kk * 16;
            uint32_t ahi[2][4], alo[2][4];
#pragma unroll
            for (int mt = 0; mt < 2; mt++) {
                int r0 = wm + mt * 16 + g4;
                const __nv_bfloat16* ph = Ahi + r0 * PAD + k + l4;
                const __nv_bfloat16* pl = Alo + r0 * PAD + k + l4;
                ahi[mt][0] = *(const uint32_t*)(ph);
                ahi[mt][1] = *(const uint32_t*)(ph + 8 * PAD);
                ahi[mt][2] = *(const uint32_t*)(ph + 8);
                ahi[mt][3] = *(const uint32_t*)(ph + 8 * PAD + 8);
                alo[mt][0] = *(const uint32_t*)(pl);
                alo[mt][1] = *(const uint32_t*)(pl + 8 * PAD);
                alo[mt][2] = *(const uint32_t*)(pl + 8);
                alo[mt][3] = *(const uint32_t*)(pl + 8 * PAD + 8);
            }
            uint32_t bhi[8][2], blo[8][2];
#pragma unroll
            for (int nt = 0; nt < 8; nt++) {
                int n = wn + nt * 8 + g4;
                const __nv_bfloat16* ph = Bhi + n * PAD + k + l4;
                const __nv_bfloat16* pl = Blo + n * PAD + k + l4;
                bhi[nt][0] = *(const uint32_t*)(ph);
                bhi[nt][1] = *(const uint32_t*)(ph + 8);
                blo[nt][0] = *(const uint32_t*)(pl);
                blo[nt][1] = *(const uint32_t*)(pl + 8);
            }
#pragma unroll
            for (int mt = 0; mt < 2; mt++)
#pragma unroll
                for (int nt = 0; nt < 8; nt++) {
                    mma_bf16(acc[mt][nt], ahi[mt], bhi[nt]);
                    mma_bf16(acc[mt][nt], ahi[mt], blo[nt]);
                    mma_bf16(acc[mt][nt], alo[mt], bhi[nt]);
                }
        }
    }

    // ---- epilogue: bias (+relu), streaming store ----
#pragma unroll
    for (int mt = 0; mt < 2; mt++) {
        int row0 = m0 + wm + mt * 16 + g4;
        int row1 = row0 + 8;
#pragma unroll
        for (int nt = 0; nt < 8; nt++) {
            int col = wn + nt * 8 + l4;
            float b0 = bias[col], b1 = bias[col + 1];
            float v0 = acc[mt][nt][0] + b0, v1 = acc[mt][nt][1] + b1;
            float v2 = acc[mt][nt][2] + b0, v3 = acc[mt][nt][3] + b1;
            if (relu) {
                v0 = fmaxf(v0, 0.f); v1 = fmaxf(v1, 0.f);
                v2 = fmaxf(v2, 0.f); v3 = fmaxf(v3, 0.f);
            }
            if (row0 < NN)
                __stcs((float2*)(out + (size_t)row0 * DD + col),
                       make_float2(v0, v1));
            if (row1 < NN)
                __stcs((float2*)(out + (size_t)row1 * DD + col),
                       make_float2(v2, v3));
        }
    }
}

// ===========================================================================
extern "C" void kernel_launch(void* const* d_in, const int* in_sizes, int n_in,
                              void* d_out, int out_size) {
    const float* h    = (const float*)d_in[0];
    const int*   esrc = (const int*)d_in[1];
    const int*   edst = (const int*)d_in[2];
    const float* fsw  = (const float*)d_in[3];
    const float* fdw  = (const float*)d_in[4];
    const float* al   = (const float*)d_in[5];
    const float* ar   = (const float*)d_in[6];
    const float* hb   = (const float*)d_in[7];
    float* out_final  = (float*)d_out;

    float *bufA, *bufB;
    int *cnt, *fill;
    cudaGetSymbolAddress((void**)&bufA, g_bufA);
    cudaGetSymbolAddress((void**)&bufB, g_bufB);
    cudaGetSymbolAddress((void**)&cnt,  g_cnt);
    cudaGetSymbolAddress((void**)&fill, g_fill);

    cudaFuncSetAttribute(gemm_agg_kernel,
                         cudaFuncAttributeMaxDynamicSharedMemorySize, SM_TOTAL);

    // ---- CSR build (R5-proven parallel scan) ----
    cudaMemsetAsync(cnt, 0, NR * NN * sizeof(int));
    cudaMemsetAsync(fill, 0, NR * NN * sizeof(int));
    hist_kernel<<<dim3((NE + 255) / 256, NR), 256>>>(edst);
    scan1_kernel<<<dim3(NBLK, NR), SCAN_B>>>();
    scan2_kernel<<<NR, 32>>>();
    scan3_kernel<<<dim3(NBLK, NR), SCAN_B>>>();
    fill_kernel<<<dim3((NE + 255) / 256, NR), 256>>>(esrc, edst);

    const int MT = (NN + 127) / 128;   // 782

    const float* x = h;
    for (int l = 0; l < NL; l++) {
        float* out = (l == 0) ? bufB : (l == 1) ? bufA : out_final;

        prep_wv_kernel<<<528, 256>>>(fsw + (size_t)l * NR * DD * DD,
                                     fdw + (size_t)l * NR * DD * DD,
                                     al + l * NR * DD, ar + l * NR * DD);
        scores_kernel<<<NN / 32, 128>>>(x);

        agg_kernel<<<dim3((NN + 7) / 8, NR), 256>>>(x);
        gemm_agg_kernel<<<MT, 256, SM_TOTAL>>>(out, hb + l * DD,
                                               l < NL - 1 ? 1 : 0);
        x = out;
    }
}

// round 11
// speedup vs baseline: 1.2995x; 1.0038x over previous
#include <cuda_runtime.h>
#include <cuda_bf16.h>
#include <math.h>
#include <cstdint>

#define NN 100000
#define NR 8
#define NE 400000
#define DD 128
#define NL 3
#define NP1 (NN + 1)

#define SCAN_B 512
#define NBLK ((NN + SCAN_B - 1) / SCAN_B)   // 196

// ---------------- device scratch (static, no allocations) ----------------
__device__ float         g_bufA[NN * DD];
__device__ float         g_bufB[NN * DD];
__device__ float         g_el[NR * NN];
__device__ float         g_er[NR * NN];
__device__ float         g_vl[NR * DD];
__device__ float         g_vr[NR * DD];
__device__ __nv_bfloat16 g_whi[NR * DD * DD];
__device__ __nv_bfloat16 g_wlo[NR * DD * DD];
__device__ __nv_bfloat16 g_yhi[(size_t)NR * NN * DD];
__device__ __nv_bfloat16 g_ylo[(size_t)NR * NN * DD];
__device__ int           g_cnt[NR * NN];
__device__ int           g_fill[NR * NN];
__device__ int           g_rowptr[NR * NP1];
__device__ int           g_bsum[NR * NBLK];
__device__ int           g_csrc[(size_t)NR * NE];

// ====================== CSR build (R5-proven) ==============================
__global__ void hist_kernel(const int* __restrict__ edst) {
    int i = blockIdx.x * 256 + threadIdx.x;
    int r = blockIdx.y;
    if (i >= NE) return;
    int d = edst[(size_t)r * NE + i];
    atomicAdd(&g_cnt[r * NN + d], 1);
}

__global__ void scan1_kernel() {
    __shared__ int sh[SCAN_B];
    int r = blockIdx.y;
    int tid = threadIdx.x;
    int i = blockIdx.x * SCAN_B + tid;
    int v = (i < NN) ? g_cnt[r * NN + i] : 0;
    sh[tid] = v;
    __syncthreads();
    for (int off = 1; off < SCAN_B; off <<= 1) {
        int t = (tid >= off) ? sh[tid - off] : 0;
        __syncthreads();
        sh[tid] += t;
        __syncthreads();
    }
    int incl = sh[tid];
    if (i < NN) g_rowptr[r * NP1 + i] = incl - v;   // exclusive within block
    if (tid == SCAN_B - 1) g_bsum[r * NBLK + blockIdx.x] = incl;
}

__global__ void scan2_kernel() {
    int r = blockIdx.x;
    if (threadIdx.x != 0) return;
    int run = 0;
    for (int b = 0; b < NBLK; b++) {
        int t = g_bsum[r * NBLK + b];
        g_bsum[r * NBLK + b] = run;
        run += t;
    }
}

__global__ void scan3_kernel() {
    int r = blockIdx.y;
    int i = blockIdx.x * SCAN_B + threadIdx.x;
    if (i < NN) g_rowptr[r * NP1 + i] += g_bsum[r * NBLK + blockIdx.x];
    if (blockIdx.x == 0 && threadIdx.x == 0) g_rowptr[r * NP1 + NN] = NE;
}

__global__ void fill_kernel(const int* __restrict__ esrc,
                            const int* __restrict__ edst) {
    int i = blockIdx.x * 256 + threadIdx.x;
    int r = blockIdx.y;
    if (i >= NE) return;
    int d = edst[(size_t)r * NE + i];
    int s = esrc[(size_t)r * NE + i];
    int pos = g_rowptr[r * NP1 + d] + atomicAdd(&g_fill[r * NN + d], 1);
    g_csrc[(size_t)r * NE + pos] = s;
}

// ---------------- fused: W hi/lo split + vl/vr vectors ---------------------
__global__ void prep_wv_kernel(const float* __restrict__ Wsrc,
                               const float* __restrict__ Wdst,
                               const float* __restrict__ al,
                               const float* __restrict__ ar) {
    int b = blockIdx.x;
    if (b < 512) {
        int i = b * 256 + threadIdx.x;
        float v = Wsrc[i];
        __nv_bfloat16 hi = __float2bfloat16_rn(v);
        float res = v - __bfloat162float(hi);
        g_whi[i] = hi;
        g_wlo[i] = __float2bfloat16_rn(res);
    } else if (threadIdx.x < 128) {
        int bb = b - 512;            // 0..15
        int r = bb >> 1;
        int k = threadIdx.x;
        const float* W = (bb & 1) ? (Wdst + r * DD * DD) : (Wsrc + r * DD * DD);
        const float* a = (bb & 1) ? (ar + r * DD) : (al + r * DD);
        float s = 0.f;
#pragma unroll 8
        for (int j = 0; j < DD; j++) s += a[j] * W[j * DD + k];
        float* o = (bb & 1) ? g_vr : g_vl;
        o[r * DD + k] = s;
    }
}

// ---------------- el[r][n] = x[n]·vl[r], er[r][n] = x[n]·vr[r] ------------
__global__ void scores_kernel(const float* __restrict__ x) {
    __shared__ float xs[32][133];
    __shared__ float vv[16][DD];
    int tid = threadIdx.x;       // 128 threads
    int n0 = blockIdx.x * 32;

    for (int i = tid; i < 16 * DD; i += 128) {
        int v = i >> 7, k = i & 127;
        vv[v][k] = (v < 8) ? g_vl[v * DD + k] : g_vr[(v - 8) * DD + k];
    }
    for (int i = tid; i < 32 * DD; i += 128) {
        int r = i >> 7, k = i & 127;
        xs[r][k] = x[(size_t)(n0 + r) * DD + k];
    }
    __syncthreads();

    int node = tid & 31;
    int v0 = (tid >> 5) * 4;
    float a0 = 0.f, a1 = 0.f, a2 = 0.f, a3 = 0.f;
#pragma unroll 8
    for (int k = 0; k < DD; k++) {
        float xv = xs[node][k];
        a0 += xv * vv[v0 + 0][k];
        a1 += xv * vv[v0 + 1][k];
        a2 += xv * vv[v0 + 2][k];
        a3 += xv * vv[v0 + 3][k];
    }
    int n = n0 + node;
    float acc[4] = {a0, a1, a2, a3};
#pragma unroll
    for (int j = 0; j < 4; j++) {
        int v = v0 + j;
        if (v < 8) g_el[v * NN + n] = acc[j];
        else       g_er[(v - 8) * NN + n] = acc[j];
    }
}

// =================== aggregation: y[r][d] = softmax-weighted mean ==========
// One warp per (dst, relation). R10-proven version (streaming y stores).
__device__ __forceinline__ uint32_t pack_bf2(__nv_bfloat16 a, __nv_bfloat16 b) {
    return (uint32_t)__bfloat16_as_ushort(a) |
           ((uint32_t)__bfloat16_as_ushort(b) << 16);
}

__global__ void __launch_bounds__(256)
agg_kernel(const float* __restrict__ x) {
    const unsigned F = 0xffffffffu;
    int lane = threadIdx.x & 31;
    int d = blockIdx.x * 8 + (threadIdx.x >> 5);
    int r = blockIdx.y;
    if (d >= NN) return;

    const int* rp = g_rowptr + r * NP1;
    const int* cs = g_csrc + (size_t)r * NE;
    const float* elr = g_el + (size_t)r * NN;
    const float4* x4 = (const float4*)x;

    int st = rp[d], en = rp[d + 1];
    float ax = 0.f, ay = 0.f, az = 0.f, aw = 0.f;
    float den = 0.f;
    if (st < en) {
        float er_d = g_er[(size_t)r * NN + d];
        for (int base = st; base < en; base += 32) {
            int c = en - base;
            if (c > 32) c = 32;
            float w = 0.f;
            int s = 0;
            if (lane < c) {
                s = cs[base + lane];
                float v = elr[s] + er_d;
                v = v > 0.f ? v : 0.2f * v;
                w = expf(v);
            }
            float ws = w;
#pragma unroll
            for (int off = 16; off; off >>= 1)
                ws += __shfl_xor_sync(F, ws, off);
            den += ws;
            for (int j = 0; j < c; j++) {
                float wj = __shfl_sync(F, w, j);
                int sj = __shfl_sync(F, s, j);
                float4 xv = x4[(size_t)sj * 32 + lane];
                ax += wj * xv.x;
                ay += wj * xv.y;
                az += wj * xv.z;
                aw += wj * xv.w;
            }
        }
        float inv = 1.f / den;
        ax *= inv; ay *= inv; az *= inv; aw *= inv;
    }
    __nv_bfloat16 h0 = __float2bfloat16_rn(ax);
    __nv_bfloat16 h1 = __float2bfloat16_rn(ay);
    __nv_bfloat16 h2 = __float2bfloat16_rn(az);
    __nv_bfloat16 h3 = __float2bfloat16_rn(aw);
    __nv_bfloat16 l0 = __float2bfloat16_rn(ax - __bfloat162float(h0));
    __nv_bfloat16 l1 = __float2bfloat16_rn(ay - __bfloat162float(h1));
    __nv_bfloat16 l2 = __float2bfloat16_rn(az - __bfloat162float(h2));
    __nv_bfloat16 l3 = __float2bfloat16_rn(aw - __bfloat162float(h3));
    size_t off = ((size_t)r * NN + d) * DD + lane * 4;
    __stcs((uint2*)(g_yhi + off), make_uint2(pack_bf2(h0, h1), pack_bf2(h2, h3)));
    __stcs((uint2*)(g_ylo + off), make_uint2(pack_bf2(l0, l1), pack_bf2(l2, l3)));
}

// =================== HMMA GEMM over aggregated y ===========================
// M-tile = 64 rows, 2 CTAs/SM: one CTA's MMA hides the other's tile loads.
// out[m] = [relu]( sum_r y[r][m] @ W[r]^T + bias ).
#define PAD 136   // bf16 elems per smem row
#define MTILE 64

#define SA_HI 0
#define SA_LO (MTILE * PAD * 2)                 // 17408
#define SB_HI (2 * MTILE * PAD * 2)             // 34816
#define SB_LO (SB_HI + 128 * PAD * 2)           // 69632
#define SM_TOTAL (SB_LO + 128 * PAD * 2)        // 104448

__device__ __forceinline__ void mma_bf16(float* c, const uint32_t* a,
                                         const uint32_t* b) {
    asm volatile(
        "mma.sync.aligned.m16n8k16.row.col.f32.bf16.bf16.f32 "
        "{%0,%1,%2,%3}, {%4,%5,%6,%7}, {%8,%9}, {%0,%1,%2,%3};"
        : "+f"(c[0]), "+f"(c[1]), "+f"(c[2]), "+f"(c[3])
        : "r"(a[0]), "r"(a[1]), "r"(a[2]), "r"(a[3]), "r"(b[0]), "r"(b[1]));
}

__global__ void __launch_bounds__(256, 2)
gemm_agg_kernel(float* __restrict__ out, const float* __restrict__ bias,
                int relu) {
    extern __shared__ char smem[];
    __nv_bfloat16* Ahi = (__nv_bfloat16*)(smem + SA_HI);
    __nv_bfloat16* Alo = (__nv_bfloat16*)(smem + SA_LO);
    __nv_bfloat16* Bhi = (__nv_bfloat16*)(smem + SB_HI);
    __nv_bfloat16* Blo = (__nv_bfloat16*)(smem + SB_LO);

    int tid = threadIdx.x;
    int wid = tid >> 5;
    int lane = tid & 31;
    int m0 = blockIdx.x * MTILE;

    // 8 warps: 2 (m) x 4 (n); warp tile 32 rows x 32 cols
    int wm = (wid >> 2) * 32;
    int wn = (wid & 3) * 32;
    int g4 = lane >> 2;
    int l4 = (lane & 3) * 2;

    float acc[2][4][4];
#pragma unroll
    for (int mt = 0; mt < 2; mt++)
#pragma unroll
        for (int nt = 0; nt < 4; nt++)
#pragma unroll
            for (int j = 0; j < 4; j++) acc[mt][nt][j] = 0.f;

    for (int r = 0; r < NR; r++) {
        __syncthreads();   // prior MMA done reading smem

        const uint4* whi4 = (const uint4*)(g_whi + (size_t)r * DD * DD);
        const uint4* wlo4 = (const uint4*)(g_wlo + (size_t)r * DD * DD);
        const uint4* yhi4 = (const uint4*)g_yhi;
        const uint4* ylo4 = (const uint4*)g_ylo;
        // B tile: 128 rows x 16 chunks = 2048
#pragma unroll
        for (int it = 0; it < 8; it++) {
            int idx = tid + it * 256;
            int row = idx >> 4, c8 = idx & 15;
            *(uint4*)(Bhi + row * PAD + c8 * 8) = whi4[idx];
            *(uint4*)(Blo + row * PAD + c8 * 8) = wlo4[idx];
        }
        // A tile: 64 rows x 16 chunks = 1024
#pragma unroll
        for (int it = 0; it < 4; it++) {
            int idx = tid + it * 256;
            int row = idx >> 4, c8 = idx & 15;
            uint4 vhi = make_uint4(0, 0, 0, 0), vlo = make_uint4(0, 0, 0, 0);
            if (m0 + row < NN) {
                size_t gi = ((size_t)r * NN + m0 + row) * 16 + c8;
                vhi = __ldcs(&yhi4[gi]);
                vlo = __ldcs(&ylo4[gi]);
            }
            *(uint4*)(Ahi + row * PAD + c8 * 8) = vhi;
            *(uint4*)(Alo + row * PAD + c8 * 8) = vlo;
        }
        __syncthreads();

        // ---- 3-term HMMA accumulate ----
#pragma unroll
        for (int kk = 0; kk < 8; kk++) {
            int k = kk * 16;
            uint32_t ahi[2][4], alo[2][4];
#pragma unroll
            for (int mt = 0; mt < 2; mt++) {
                int r0 = wm + mt * 16 + g4;
                const __nv_bfloat16* ph = Ahi + r0 * PAD + k + l4;
                const __nv_bfloat16* pl = Alo + r0 * PAD + k + l4;
                ahi[mt][0] = *(const uint32_t*)(ph);
                ahi[mt][1] = *(const uint32_t*)(ph + 8 * PAD);
                ahi[mt][2] = *(const uint32_t*)(ph + 8);
                ahi[mt][3] = *(const uint32_t*)(ph + 8 * PAD + 8);
                alo[mt][0] = *(const uint32_t*)(pl);
                alo[mt][1] = *(const uint32_t*)(pl + 8 * PAD);
                alo[mt][2] = *(const uint32_t*)(pl + 8);
                alo[mt][3] = *(const uint32_t*)(pl + 8 * PAD + 8);
            }
            uint32_t bhi[4][2], blo[4][2];
#pragma unroll
            for (int nt = 0; nt < 4; nt++) {
                int n = wn + nt * 8 + g4;
                const __nv_bfloat16* ph = Bhi + n * PAD + k + l4;
                const __nv_bfloat16* pl = Blo + n * PAD + k + l4;
                bhi[nt][0] = *(const uint32_t*)(ph);
                bhi[nt][1] = *(const uint32_t*)(ph + 8);
                blo[nt][0] = *(const uint32_t*)(pl);
                blo[nt][1] = *(const uint32_t*)(pl + 8);
            }
#pragma unroll
            for (int mt = 0; mt < 2; mt++)
#pragma unroll
                for (int nt = 0; nt < 4; nt++) {
                    mma_bf16(acc[mt][nt], ahi[mt], bhi[nt]);
                    mma_bf16(acc[mt][nt], ahi[mt], blo[nt]);
                    mma_bf16(acc[mt][nt], alo[mt], bhi[nt]);
                }
        }
    }

    // ---- epilogue: bias (+relu), streaming store ----
#pragma unroll
    for (int mt = 0; mt < 2; mt++) {
        int row0 = m0 + wm + mt * 16 + g4;
        int row1 = row0 + 8;
#pragma unroll
        for (int nt = 0; nt < 4; nt++) {
            int col = wn + nt * 8 + l4;
            float b0 = bias[col], b1 = bias[col + 1];
            float v0 = acc[mt][nt][0] + b0, v1 = acc[mt][nt][1] + b1;
            float v2 = acc[mt][nt][2] + b0, v3 = acc[mt][nt][3] + b1;
            if (relu) {
                v0 = fmaxf(v0, 0.f); v1 = fmaxf(v1, 0.f);
                v2 = fmaxf(v2, 0.f); v3 = fmaxf(v3, 0.f);
            }
            if (row0 < NN)
                __stcs((float2*)(out + (size_t)row0 * DD + col),
                       make_float2(v0, v1));
            if (row1 < NN)
                __stcs((float2*)(out + (size_t)row1 * DD + col),
                       make_float2(v2, v3));
        }
    }
}

// ===========================================================================
extern "C" void kernel_launch(void* const* d_in, const int* in_sizes, int n_in,
                              void* d_out, int out_size) {
    const float* h    = (const float*)d_in[0];
    const int*   esrc = (const int*)d_in[1];
    const int*   edst = (const int*)d_in[2];
    const float* fsw  = (const float*)d_in[3];
    const float* fdw  = (const float*)d_in[4];
    const float* al   = (const float*)d_in[5];
    const float* ar   = (const float*)d_in[6];
    const float* hb   = (const float*)d_in[7];
    float* out_final  = (float*)d_out;

    float *bufA, *bufB;
    int *cnt, *fill;
    cudaGetSymbolAddress((void**)&bufA, g_bufA);
    cudaGetSymbolAddress((void**)&bufB, g_bufB);
    cudaGetSymbolAddress((void**)&cnt,  g_cnt);
    cudaGetSymbolAddress((void**)&fill, g_fill);

    cudaFuncSetAttribute(gemm_agg_kernel,
                         cudaFuncAttributeMaxDynamicSharedMemorySize, SM_TOTAL);

    // ---- CSR build (R5-proven parallel scan) ----
    cudaMemsetAsync(cnt, 0, NR * NN * sizeof(int));
    cudaMemsetAsync(fill, 0, NR * NN * sizeof(int));
    hist_kernel<<<dim3((NE + 255) / 256, NR), 256>>>(edst);
    scan1_kernel<<<dim3(NBLK, NR), SCAN_B>>>();
    scan2_kernel<<<NR, 32>>>();
    scan3_kernel<<<dim3(NBLK, NR), SCAN_B>>>();
    fill_kernel<<<dim3((NE + 255) / 256, NR), 256>>>(esrc, edst);

    const int MT = (NN + MTILE - 1) / MTILE;   // 1563

    const float* x = h;
    for (int l = 0; l < NL; l++) {
        float* out = (l == 0) ? bufB : (l == 1) ? bufA : out_final;

        prep_wv_kernel<<<528, 256>>>(fsw + (size_t)l * NR * DD * DD,
                                     fdw + (size_t)l * NR * DD * DD,
                                     al + l * NR * DD, ar + l * NR * DD);
        scores_kernel<<<NN / 32, 128>>>(x);

        agg_kernel<<<dim3((NN + 7) / 8, NR), 256>>>(x);
        gemm_agg_kernel<<<MT, 256, SM_TOTAL>>>(out, hb + l * DD,
                                               l < NL - 1 ? 1 : 0);
        x = out;
    }
}